// round 15
// baseline (speedup 1.0000x reference)
#include <cuda_runtime.h>
#include <cuda_bf16.h>
#include <cstdint>
#include <cstddef>

// ---------------- problem constants ----------------
constexpr int TT   = 2048;
constexpr int HH   = 2048;
constexpr int EE   = 64;
constexpr int KTOP = 8;
constexpr int II   = 768;
constexpr int NHH  = 16;
constexpr int DHH  = 128;
constexpr int SII  = 4096;
constexpr int CAPP = 512;

// ---------------- scratch (device globals: allocation-free) ----------------
// fp32
__device__ float g_hn1   [(size_t)TT*HH];
__device__ float g_qkv   [(size_t)TT*3*HH];
__device__ float g_scores[(size_t)NHH*TT*TT];
__device__ float g_attn  [(size_t)TT*HH];
__device__ float g_x2    [(size_t)TT*HH];
__device__ float g_hn2   [(size_t)TT*HH];
__device__ float g_logits[(size_t)TT*EE];
__device__ int   g_ids   [TT*KTOP];
__device__ float g_wts   [TT*KTOP];
__device__ int   g_pos   [TT*KTOP];
__device__ int   g_cnt   [EE];
__device__ float g_gu    [(size_t)EE*CAPP*2*II];
__device__ float g_y     [(size_t)EE*CAPP*HH];
__device__ float g_sgu   [(size_t)TT*2*SII];
__device__ float g_sres  [(size_t)TT*HH];
// packed bf16 hi/lo (hi in low 16 bits, lo in high 16 bits)
__device__ uint32_t p_hn2 [(size_t)TT*HH];
__device__ uint32_t p_buf [(size_t)EE*CAPP*HH];
__device__ uint32_t p_eact[(size_t)EE*CAPP*II];
__device__ uint32_t p_sact[(size_t)TT*SII];
__device__ uint32_t p_w1  [(size_t)EE*2*II*HH];
__device__ uint32_t p_w2  [(size_t)EE*HH*II];
__device__ uint32_t p_sw13[(size_t)2*SII*HH];
__device__ uint32_t p_sw2 [(size_t)HH*SII];

// ---------------- shared GEMM tiling ----------------
constexpr int BM  = 128, BN = 128, BKT = 16;
constexpr int ASTR   = BKT + 4;   // [row][k] tiles, stride 20 words
constexpr int BSTR_N = BN  + 8;   // tf32 NN B tile [k][n], stride 136

__device__ __forceinline__ uint32_t smaddr(const void* p) {
    return (uint32_t)__cvta_generic_to_shared(p);
}
__device__ __forceinline__ void cp16(uint32_t dst, const void* src, bool pred) {
    int sz = pred ? 16 : 0;
    asm volatile("cp.async.cg.shared.global [%0], [%1], 16, %2;\n"
                 :: "r"(dst), "l"(src), "r"(sz));
}
// split fp32 -> tf32 hi + tf32 lo (near-fp32 when recombined via 3 MMAs)
__device__ __forceinline__ void tf32split(float x, uint32_t& h, uint32_t& l) {
    asm("cvt.rna.tf32.f32 %0, %1;" : "=r"(h) : "f"(x));
    float r = x - __uint_as_float(h);
    asm("cvt.rna.tf32.f32 %0, %1;" : "=r"(l) : "f"(r));
}
// pack fp32 -> (bf16 hi | bf16 lo << 16)
__device__ __forceinline__ uint32_t packhl(float x) {
    __nv_bfloat16 hb = __float2bfloat16(x);
    unsigned hu = (unsigned)__bfloat16_as_ushort(hb);
    float hf = __uint_as_float(hu << 16);
    __nv_bfloat16 lb = __float2bfloat16(x - hf);
    unsigned lu = (unsigned)__bfloat16_as_ushort(lb);
    return hu | (lu << 16);
}
__device__ __forceinline__ void mma8_tf32(float c[4], const uint32_t a[4], const uint32_t b[2]) {
    asm volatile("mma.sync.aligned.m16n8k8.row.col.f32.tf32.tf32.f32 "
                 "{%0,%1,%2,%3}, {%4,%5,%6,%7}, {%8,%9}, {%0,%1,%2,%3};\n"
                 : "+f"(c[0]), "+f"(c[1]), "+f"(c[2]), "+f"(c[3])
                 : "r"(a[0]), "r"(a[1]), "r"(a[2]), "r"(a[3]),
                   "r"(b[0]), "r"(b[1]));
}
__device__ __forceinline__ void mma16_bf16(float c[4], const uint32_t a[4], const uint32_t b[2]) {
    asm volatile("mma.sync.aligned.m16n8k16.row.col.f32.bf16.bf16.f32 "
                 "{%0,%1,%2,%3}, {%4,%5,%6,%7}, {%8,%9}, {%0,%1,%2,%3};\n"
                 : "+f"(c[0]), "+f"(c[1]), "+f"(c[2]), "+f"(c[3])
                 : "r"(a[0]), "r"(a[1]), "r"(a[2]), "r"(a[3]),
                   "r"(b[0]), "r"(b[1]));
}

// ================= tf32x3 GEMM (fp32 in/out, near-fp32 accuracy) =================
// C[b] = alpha * A[b] * op(B[b]) (+ R[b]); op = B (KxN, !TB) or B^T (NxK rows, TB)
template <bool TB>
__global__ __launch_bounds__(256, 1)
void tgemm_tf32x3(const float* __restrict__ A, int lda, long long sA,
                  const float* __restrict__ B, int ldb, long long sB,
                  float*       __restrict__ C, int ldc, long long sC,
                  const float* __restrict__ R, int ldr, long long sR,
                  int M, int N, int Kd, float alpha,
                  const int* __restrict__ rowLimit)
{
    const int bz = blockIdx.z;
    if (rowLimit != nullptr && (int)(blockIdx.y * BM) >= rowLimit[bz]) return;
    A += (long long)bz * sA;
    B += (long long)bz * sB;
    C += (long long)bz * sC;
    if (R) R += (long long)bz * sR;

    constexpr int BS_ELEMS = TB ? BN * ASTR : BKT * BSTR_N;
    __shared__ float As[2][BM * ASTR];
    __shared__ float Bs[2][BS_ELEMS];

    const int tid  = threadIdx.x;
    const int lane = tid & 31;
    const int warp = tid >> 5;
    const int g    = lane >> 2;
    const int tg   = lane & 3;
    const int wm   = (warp & 3) * 32;
    const int wn   = (warp >> 2) * 64;
    const int row0 = blockIdx.y * BM;
    const int col0 = blockIdx.x * BN;

    float acc[2][8][4];
#pragma unroll
    for (int i = 0; i < 2; i++)
#pragma unroll
        for (int j = 0; j < 8; j++)
#pragma unroll
            for (int v = 0; v < 4; v++) acc[i][j][v] = 0.f;

    auto load_stage = [&](int k0, int bufi) {
        const int mr = tid >> 2;
        const int k4 = (tid & 3) * 4;
        {
            bool p0 = (row0 + mr) < M;
            cp16(smaddr(&As[bufi][mr * ASTR + k4]),
                 p0 ? A + (long long)(row0 + mr) * lda + k0 + k4 : A, p0);
            bool p1 = (row0 + mr + 64) < M;
            cp16(smaddr(&As[bufi][(mr + 64) * ASTR + k4]),
                 p1 ? A + (long long)(row0 + mr + 64) * lda + k0 + k4 : A, p1);
        }
        if (TB) {
            bool p0 = (col0 + mr) < N;
            cp16(smaddr(&Bs[bufi][mr * ASTR + k4]),
                 p0 ? B + (long long)(col0 + mr) * ldb + k0 + k4 : B, p0);
            bool p1 = (col0 + mr + 64) < N;
            cp16(smaddr(&Bs[bufi][(mr + 64) * ASTR + k4]),
                 p1 ? B + (long long)(col0 + mr + 64) * ldb + k0 + k4 : B, p1);
        } else {
            const int kr = tid >> 5;
            const int n4 = lane * 4;
            bool p = (col0 + n4) < N;
            cp16(smaddr(&Bs[bufi][kr * BSTR_N + n4]),
                 p ? B + (long long)(k0 + kr) * ldb + col0 + n4 : B, p);
            cp16(smaddr(&Bs[bufi][(kr + 8) * BSTR_N + n4]),
                 p ? B + (long long)(k0 + kr + 8) * ldb + col0 + n4 : B, p);
        }
    };

    load_stage(0, 0);
    asm volatile("cp.async.commit_group;\n");

    const int S = Kd >> 4;
    int buf = 0;
    for (int s = 0; s < S; s++) {
        asm volatile("cp.async.wait_group 0;\n");
        __syncthreads();
        if (s + 1 < S) {
            load_stage((s + 1) * BKT, buf ^ 1);
            asm volatile("cp.async.commit_group;\n");
        }
        const float* as = As[buf];
        const float* bs = Bs[buf];
#pragma unroll
        for (int ks = 0; ks < 2; ks++) {
            const int kb = ks * 8;
            uint32_t ah[2][4], al[2][4];
#pragma unroll
            for (int i = 0; i < 2; i++) {
                const int m = wm + i * 16 + g;
                tf32split(as[m       * ASTR + kb + tg],     ah[i][0], al[i][0]);
                tf32split(as[(m + 8) * ASTR + kb + tg],     ah[i][1], al[i][1]);
                tf32split(as[m       * ASTR + kb + tg + 4], ah[i][2], al[i][2]);
                tf32split(as[(m + 8) * ASTR + kb + tg + 4], ah[i][3], al[i][3]);
            }
#pragma unroll
            for (int j = 0; j < 8; j++) {
                const int n = wn + j * 8 + g;
                uint32_t bh[2], bl[2];
                if (TB) {
                    tf32split(bs[n * ASTR + kb + tg],     bh[0], bl[0]);
                    tf32split(bs[n * ASTR + kb + tg + 4], bh[1], bl[1]);
                } else {
                    tf32split(bs[(kb + tg)     * BSTR_N + n], bh[0], bl[0]);
                    tf32split(bs[(kb + tg + 4) * BSTR_N + n], bh[1], bl[1]);
                }
#pragma unroll
                for (int i = 0; i < 2; i++) {
                    mma8_tf32(acc[i][j], ah[i], bh);
                    mma8_tf32(acc[i][j], ah[i], bl);
                    mma8_tf32(acc[i][j], al[i], bh);
                }
            }
        }
        __syncthreads();
        buf ^= 1;
    }

#pragma unroll
    for (int i = 0; i < 2; i++) {
#pragma unroll
        for (int j = 0; j < 8; j++) {
            const int r = row0 + wm + i * 16 + g;
            const int c = col0 + wn + j * 8 + tg * 2;
            if (c < N) {
                if (r < M) {
                    float2 v = make_float2(alpha * acc[i][j][0], alpha * acc[i][j][1]);
                    if (R) {
                        const float2 rr = *reinterpret_cast<const float2*>(&R[(long long)r * ldr + c]);
                        v.x += rr.x; v.y += rr.y;
                    }
                    *reinterpret_cast<float2*>(&C[(long long)r * ldc + c]) = v;
                }
                if (r + 8 < M) {
                    float2 v = make_float2(alpha * acc[i][j][2], alpha * acc[i][j][3]);
                    if (R) {
                        const float2 rr = *reinterpret_cast<const float2*>(&R[(long long)(r + 8) * ldr + c]);
                        v.x += rr.x; v.y += rr.y;
                    }
                    *reinterpret_cast<float2*>(&C[(long long)(r + 8) * ldc + c]) = v;
                }
            }
        }
    }
}

// ================= bf16x3 GEMM (packed hi/lo in, fp32 out; TB only) =================
// C[b] = A[b] * B[b]^T (+ R[b]); A,B are packed uint32 (bf16 hi | bf16 lo<<16)
__global__ __launch_bounds__(256, 1)
void tgemm_bf16x3(const uint32_t* __restrict__ A, int lda, long long sA,
                  const uint32_t* __restrict__ B, int ldb, long long sB,
                  float*          __restrict__ C, int ldc, long long sC,
                  const float*    __restrict__ R, int ldr, long long sR,
                  int M, int N, int Kd,
                  const int* __restrict__ rowLimit)
{
    const int bz = blockIdx.z;
    if (rowLimit != nullptr && (int)(blockIdx.y * BM) >= rowLimit[bz]) return;
    A += (long long)bz * sA;
    B += (long long)bz * sB;
    C += (long long)bz * sC;
    if (R) R += (long long)bz * sR;

    __shared__ uint32_t As[2][BM * ASTR];
    __shared__ uint32_t Bs[2][BN * ASTR];

    const int tid  = threadIdx.x;
    const int lane = tid & 31;
    const int warp = tid >> 5;
    const int g    = lane >> 2;
    const int tg   = lane & 3;
    const int wm   = (warp & 3) * 32;
    const int wn   = (warp >> 2) * 64;
    const int row0 = blockIdx.y * BM;
    const int col0 = blockIdx.x * BN;

    float acc[2][8][4];
#pragma unroll
    for (int i = 0; i < 2; i++)
#pragma unroll
        for (int j = 0; j < 8; j++)
#pragma unroll
            for (int v = 0; v < 4; v++) acc[i][j][v] = 0.f;

    auto load_stage = [&](int k0, int bufi) {
        const int mr = tid >> 2;
        const int k4 = (tid & 3) * 4;
        bool p0 = (row0 + mr) < M;
        cp16(smaddr(&As[bufi][mr * ASTR + k4]),
             p0 ? A + (long long)(row0 + mr) * lda + k0 + k4 : A, p0);
        bool p1 = (row0 + mr + 64) < M;
        cp16(smaddr(&As[bufi][(mr + 64) * ASTR + k4]),
             p1 ? A + (long long)(row0 + mr + 64) * lda + k0 + k4 : A, p1);
        bool q0 = (col0 + mr) < N;
        cp16(smaddr(&Bs[bufi][mr * ASTR + k4]),
             q0 ? B + (long long)(col0 + mr) * ldb + k0 + k4 : B, q0);
        bool q1 = (col0 + mr + 64) < N;
        cp16(smaddr(&Bs[bufi][(mr + 64) * ASTR + k4]),
             q1 ? B + (long long)(col0 + mr + 64) * ldb + k0 + k4 : B, q1);
    };

    load_stage(0, 0);
    asm volatile("cp.async.commit_group;\n");

    const int S = Kd >> 4;
    int buf = 0;
    for (int s = 0; s < S; s++) {
        asm volatile("cp.async.wait_group 0;\n");
        __syncthreads();
        if (s + 1 < S) {
            load_stage((s + 1) * BKT, buf ^ 1);
            asm volatile("cp.async.commit_group;\n");
        }
        const uint32_t* as = As[buf];
        const uint32_t* bs = Bs[buf];

        uint32_t ah[2][4], al[2][4];
#pragma unroll
        for (int i = 0; i < 2; i++) {
            const int m = wm + i * 16 + g;
            uint2 w0 = *reinterpret_cast<const uint2*>(&as[m       * ASTR + 2 * tg]);
            uint2 w1 = *reinterpret_cast<const uint2*>(&as[(m + 8) * ASTR + 2 * tg]);
            uint2 w2 = *reinterpret_cast<const uint2*>(&as[m       * ASTR + 2 * tg + 8]);
            uint2 w3 = *reinterpret_cast<const uint2*>(&as[(m + 8) * ASTR + 2 * tg + 8]);
            ah[i][0] = __byte_perm(w0.x, w0.y, 0x5410); al[i][0] = __byte_perm(w0.x, w0.y, 0x7632);
            ah[i][1] = __byte_perm(w1.x, w1.y, 0x5410); al[i][1] = __byte_perm(w1.x, w1.y, 0x7632);
            ah[i][2] = __byte_perm(w2.x, w2.y, 0x5410); al[i][2] = __byte_perm(w2.x, w2.y, 0x7632);
            ah[i][3] = __byte_perm(w3.x, w3.y, 0x5410); al[i][3] = __byte_perm(w3.x, w3.y, 0x7632);
        }
#pragma unroll
        for (int j = 0; j < 8; j++) {
            const int n = wn + j * 8 + g;
            uint2 q0 = *reinterpret_cast<const uint2*>(&bs[n * ASTR + 2 * tg]);
            uint2 q1 = *reinterpret_cast<const uint2*>(&bs[n * ASTR + 2 * tg + 8]);
            uint32_t bh[2], bl[2];
            bh[0] = __byte_perm(q0.x, q0.y, 0x5410); bl[0] = __byte_perm(q0.x, q0.y, 0x7632);
            bh[1] = __byte_perm(q1.x, q1.y, 0x5410); bl[1] = __byte_perm(q1.x, q1.y, 0x7632);
#pragma unroll
            for (int i = 0; i < 2; i++) {
                mma16_bf16(acc[i][j], ah[i], bh);
                mma16_bf16(acc[i][j], ah[i], bl);
                mma16_bf16(acc[i][j], al[i], bh);
            }
        }
        __syncthreads();
        buf ^= 1;
    }

#pragma unroll
    for (int i = 0; i < 2; i++) {
#pragma unroll
        for (int j = 0; j < 8; j++) {
            const int r = row0 + wm + i * 16 + g;
            const int c = col0 + wn + j * 8 + tg * 2;
            if (c < N) {
                if (r < M) {
                    float2 v = make_float2(acc[i][j][0], acc[i][j][1]);
                    if (R) {
                        const float2 rr = *reinterpret_cast<const float2*>(&R[(long long)r * ldr + c]);
                        v.x += rr.x; v.y += rr.y;
                    }
                    *reinterpret_cast<float2*>(&C[(long long)r * ldc + c]) = v;
                }
                if (r + 8 < M) {
                    float2 v = make_float2(acc[i][j][2], acc[i][j][3]);
                    if (R) {
                        const float2 rr = *reinterpret_cast<const float2*>(&R[(long long)(r + 8) * ldr + c]);
                        v.x += rr.x; v.y += rr.y;
                    }
                    *reinterpret_cast<float2*>(&C[(long long)(r + 8) * ldc + c]) = v;
                }
            }
        }
    }
}

// ---------------- pack fp32 -> bf16 hi/lo uint32 ----------------
__global__ void pack_kernel(const float4* __restrict__ src, uint4* __restrict__ dst, long long n4)
{
    long long i = (long long)blockIdx.x * blockDim.x + threadIdx.x;
    long long stride = (long long)gridDim.x * blockDim.x;
    for (; i < n4; i += stride) {
        float4 v = src[i];
        uint4 o;
        o.x = packhl(v.x); o.y = packhl(v.y); o.z = packhl(v.z); o.w = packhl(v.w);
        dst[i] = o;
    }
}

// ---------------- RMSNorm (optional fp32 and packed outputs) ----------------
__global__ void rmsnorm_kernel(const float* __restrict__ x, const float* __restrict__ g,
                               float* __restrict__ outf, uint32_t* __restrict__ outp)
{
    int t = blockIdx.x, tid = threadIdx.x;
    const float* xr = x + (size_t)t * HH;
    __shared__ float red[256];
    float s = 0.f;
    for (int i = tid; i < HH; i += 256) { float v = xr[i]; s += v * v; }
    red[tid] = s; __syncthreads();
    for (int st = 128; st > 0; st >>= 1) { if (tid < st) red[tid] += red[tid + st]; __syncthreads(); }
    float inv = rsqrtf(red[0] / (float)HH + 1e-6f);
    for (int i = tid; i < HH; i += 256) {
        float v = xr[i] * inv * g[i];
        if (outf) outf[(size_t)t * HH + i] = v;
        if (outp) outp[(size_t)t * HH + i] = packhl(v);
    }
}

// ---------------- causal softmax (in-place on one hq row) ----------------
__global__ void softmax_causal_kernel(float* __restrict__ scores)
{
    size_t rowid = blockIdx.x;
    int q = (int)(rowid % TT);
    float* row = scores + rowid * (size_t)TT;
    int len = q + 1;
    int tid = threadIdx.x;
    __shared__ float red[256];

    float m = -3.4e38f;
    for (int i = tid; i < len; i += 256) m = fmaxf(m, row[i]);
    red[tid] = m; __syncthreads();
    for (int st = 128; st > 0; st >>= 1) { if (tid < st) red[tid] = fmaxf(red[tid], red[tid + st]); __syncthreads(); }
    m = red[0]; __syncthreads();

    float s = 0.f;
    for (int i = tid; i < len; i += 256) { float e = __expf(row[i] - m); row[i] = e; s += e; }
    red[tid] = s; __syncthreads();
    for (int st = 128; st > 0; st >>= 1) { if (tid < st) red[tid] += red[tid + st]; __syncthreads(); }
    float inv = 1.0f / red[0];

    for (int i = tid; i < len; i += 256) row[i] *= inv;
    for (int i = len + tid; i < TT; i += 256) row[i] = 0.f;
}

// ---------------- gating: top-8 on logits, softmax weights over selected ----------------
__global__ void gate_topk_kernel(const float* __restrict__ logits,
                                 int* __restrict__ ids, float* __restrict__ wts)
{
    int t = blockIdx.x, lane = threadIdx.x;
    float v0 = logits[(size_t)t * EE + lane];
    float v1 = logits[(size_t)t * EE + 32 + lane];
    float selv[KTOP]; int seli[KTOP];
    for (int r = 0; r < KTOP; r++) {
        float bv; int bi;
        if (v0 >= v1) { bv = v0; bi = lane; } else { bv = v1; bi = lane + 32; }
        for (int o = 16; o > 0; o >>= 1) {
            float ov = __shfl_xor_sync(0xffffffffu, bv, o);
            int   oi = __shfl_xor_sync(0xffffffffu, bi, o);
            if (ov > bv || (ov == bv && oi < bi)) { bv = ov; bi = oi; }
        }
        selv[r] = bv; seli[r] = bi;
        if (bi == lane)      v0 = -3.4e38f;
        if (bi == lane + 32) v1 = -3.4e38f;
    }
    if (lane == 0) {
        float m = selv[0], s = 0.f, w[KTOP];
        for (int r = 0; r < KTOP; r++) { w[r] = __expf(selv[r] - m); s += w[r]; }
        float inv = 1.f / s;
        for (int r = 0; r < KTOP; r++) { ids[t * KTOP + r] = seli[r]; wts[t * KTOP + r] = w[r] * inv; }
    }
}

// ---------------- per-expert capacity scan over flattened (t,k) order ----------------
__global__ void dispatch_kernel(const int* __restrict__ ids, int* __restrict__ pos,
                                int* __restrict__ cnt)
{
    int e = blockIdx.x;
    int tid = threadIdx.x, lane = tid & 31, w = tid >> 5;
    __shared__ int wt[8];
    __shared__ int base;
    if (tid == 0) base = 0;
    __syncthreads();
    for (int f0 = 0; f0 < TT * KTOP; f0 += 256) {
        int f = f0 + tid;
        int match = (ids[f] == e) ? 1 : 0;
        unsigned m = __ballot_sync(0xffffffffu, match);
        if (lane == 0) wt[w] = __popc(m);
        int wexcl = __popc(m & ((1u << lane) - 1u));
        __syncthreads();
        int off = 0; for (int i = 0; i < w; i++) off += wt[i];
        int tot = 0; for (int i = 0; i < 8; i++) tot += wt[i];
        if (match) {
            int p = base + off + wexcl;
            pos[f] = (p < CAPP) ? p : -1;
        }
        __syncthreads();
        if (tid == 0) base += tot;
        __syncthreads();
    }
    if (tid == 0) cnt[e] = (base < CAPP) ? base : CAPP;
}

// ---------------- zero / gather / activations / combine ----------------
__global__ void zero_kernel(uint4* __restrict__ p, long long n4)
{
    long long i = (long long)blockIdx.x * blockDim.x + threadIdx.x;
    long long stride = (long long)gridDim.x * blockDim.x;
    for (; i < n4; i += stride) p[i] = make_uint4(0u, 0u, 0u, 0u);
}

__global__ void gather_kernel(const uint32_t* __restrict__ hn2p, const int* __restrict__ ids,
                              const int* __restrict__ pos, uint32_t* __restrict__ buf)
{
    int f = blockIdx.x;
    int p = pos[f];
    if (p < 0) return;
    int e = ids[f], t = f / KTOP;
    const uint4* src = reinterpret_cast<const uint4*>(hn2p + (size_t)t * HH);
    uint4* dst = reinterpret_cast<uint4*>(buf + ((size_t)e * CAPP + p) * HH);
    for (int i = threadIdx.x; i < HH / 4; i += 256) dst[i] = src[i];
}

__global__ void expert_act_kernel(const float* __restrict__ gu, uint32_t* __restrict__ act,
                                  const int* __restrict__ cnt)
{
    int ec = blockIdx.x;
    int c = ec & (CAPP - 1);
    int e = ec >> 9;
    if (c >= cnt[e]) return;
    const float* gr = gu + (size_t)ec * (2 * II);
    uint32_t* ar = act + (size_t)ec * II;
    for (int i = threadIdx.x; i < II; i += 256) {
        float gv = gr[i], uv = gr[II + i];
        ar[i] = packhl(gv / (1.f + __expf(-gv)) * uv);
    }
}

__global__ void shared_act_kernel(const float* __restrict__ sgu, uint32_t* __restrict__ sact)
{
    int t = blockIdx.x;
    const float* gr = sgu + (size_t)t * (2 * SII);
    uint32_t* ar = sact + (size_t)t * SII;
    for (int i = threadIdx.x; i < SII; i += 256) {
        float gv = gr[i], uv = gr[SII + i];
        ar[i] = packhl(gv / (1.f + __expf(-gv)) * uv);
    }
}

__global__ void combine_kernel(const float* __restrict__ sres, const float* __restrict__ y,
                               const int* __restrict__ ids, const float* __restrict__ wts,
                               const int* __restrict__ pos, float* __restrict__ out)
{
    int t = blockIdx.x;
    __shared__ int se[KTOP], sp[KTOP];
    __shared__ float sw[KTOP];
    if (threadIdx.x < KTOP) {
        se[threadIdx.x] = ids[t * KTOP + threadIdx.x];
        sp[threadIdx.x] = pos[t * KTOP + threadIdx.x];
        sw[threadIdx.x] = wts[t * KTOP + threadIdx.x];
    }
    __syncthreads();
    for (int h = threadIdx.x; h < HH; h += 256) {
        float acc = sres[(size_t)t * HH + h];
#pragma unroll
        for (int k = 0; k < KTOP; k++)
            if (sp[k] >= 0)
                acc += y[((size_t)se[k] * CAPP + sp[k]) * HH + h] * sw[k];
        out[(size_t)t * HH + h] = acc;
    }
}

// ---------------- host-side launchers ----------------
static inline void gemm_t3(bool tb,
    const float* A, int lda, long long sA,
    const float* B, int ldb, long long sB,
    float*       C, int ldc, long long sC,
    const float* R, int ldr, long long sR,
    int M, int N, int Kd, float alpha, const int* rl, int batch)
{
    dim3 grid((N + BN - 1) / BN, (M + BM - 1) / BM, batch);
    if (tb) tgemm_tf32x3<true ><<<grid, 256>>>(A, lda, sA, B, ldb, sB, C, ldc, sC, R, ldr, sR, M, N, Kd, alpha, rl);
    else    tgemm_tf32x3<false><<<grid, 256>>>(A, lda, sA, B, ldb, sB, C, ldc, sC, R, ldr, sR, M, N, Kd, alpha, rl);
}
static inline void gemm_b3(
    const uint32_t* A, int lda, long long sA,
    const uint32_t* B, int ldb, long long sB,
    float*          C, int ldc, long long sC,
    const float*    R, int ldr, long long sR,
    int M, int N, int Kd, const int* rl, int batch)
{
    dim3 grid((N + BN - 1) / BN, (M + BM - 1) / BM, batch);
    tgemm_bf16x3<<<grid, 256>>>(A, lda, sA, B, ldb, sB, C, ldc, sC, R, ldr, sR, M, N, Kd, rl);
}

extern "C" void kernel_launch(void* const* d_in, const int* in_sizes, int n_in,
                              void* d_out, int out_size)
{
    const float* x      = (const float*)d_in[0];
    const float* w_qkv  = (const float*)d_in[1];
    const float* w_o    = (const float*)d_in[2];
    const float* pre_g  = (const float*)d_in[3];
    const float* post_g = (const float*)d_in[4];
    const float* w_gate = (const float*)d_in[5];
    const float* w1     = (const float*)d_in[6];
    const float* w2     = (const float*)d_in[7];
    const float* sw13   = (const float*)d_in[8];
    const float* sw2    = (const float*)d_in[9];
    float* out = (float*)d_out;

    float *hn1, *qkv, *scores, *attn, *x2, *hn2, *logits, *wts, *gu, *y, *sgu, *sres;
    int *ids, *pos, *cnt;
    uint32_t *phn2, *pbuf, *peact, *psact, *pw1, *pw2, *psw13, *psw2;
    cudaGetSymbolAddress((void**)&hn1,    g_hn1);
    cudaGetSymbolAddress((void**)&qkv,    g_qkv);
    cudaGetSymbolAddress((void**)&scores, g_scores);
    cudaGetSymbolAddress((void**)&attn,   g_attn);
    cudaGetSymbolAddress((void**)&x2,     g_x2);
    cudaGetSymbolAddress((void**)&hn2,    g_hn2);
    cudaGetSymbolAddress((void**)&logits, g_logits);
    cudaGetSymbolAddress((void**)&ids,    g_ids);
    cudaGetSymbolAddress((void**)&wts,    g_wts);
    cudaGetSymbolAddress((void**)&pos,    g_pos);
    cudaGetSymbolAddress((void**)&cnt,    g_cnt);
    cudaGetSymbolAddress((void**)&gu,     g_gu);
    cudaGetSymbolAddress((void**)&y,      g_y);
    cudaGetSymbolAddress((void**)&sgu,    g_sgu);
    cudaGetSymbolAddress((void**)&sres,   g_sres);
    cudaGetSymbolAddress((void**)&phn2,   p_hn2);
    cudaGetSymbolAddress((void**)&pbuf,   p_buf);
    cudaGetSymbolAddress((void**)&peact,  p_eact);
    cudaGetSymbolAddress((void**)&psact,  p_sact);
    cudaGetSymbolAddress((void**)&pw1,    p_w1);
    cudaGetSymbolAddress((void**)&pw2,    p_w2);
    cudaGetSymbolAddress((void**)&psw13,  p_sw13);
    cudaGetSymbolAddress((void**)&psw2,   p_sw2);

    const float sc = 0.08838834764831845f;   // DH^-0.5

    // 0) pack MoE/shared weights into bf16 hi/lo
    pack_kernel<<<4096, 256>>>((const float4*)w1,   (uint4*)pw1,   (long long)EE * 2 * II * HH / 4);
    pack_kernel<<<4096, 256>>>((const float4*)w2,   (uint4*)pw2,   (long long)EE * HH * II / 4);
    pack_kernel<<<2048, 256>>>((const float4*)sw13, (uint4*)psw13, (long long)2 * SII * HH / 4);
    pack_kernel<<<2048, 256>>>((const float4*)sw2,  (uint4*)psw2,  (long long)HH * SII / 4);

    // 1) pre-LN (fp32 only; consumed by tf32x3 qkv GEMM)
    rmsnorm_kernel<<<TT, 256>>>(x, pre_g, hn1, nullptr);
    // 2) qkv = hn1 @ w_qkv             (tf32x3 NN)
    gemm_t3(false, hn1, HH, 0, w_qkv, 3 * HH, 0, qkv, 3 * HH, 0, nullptr, 0, 0,
            TT, 3 * HH, HH, 1.f, nullptr, 1);
    // 3) scores[h] = Q_h K_h^T * sc    (tf32x3 NT, batched over heads)
    gemm_t3(true, qkv, 3 * HH, DHH, qkv + HH, 3 * HH, DHH, scores, TT, (long long)TT * TT,
            nullptr, 0, 0, TT, TT, DHH, sc, nullptr, NHH);
    // 4) causal softmax in-place
    softmax_causal_kernel<<<NHH * TT, 256>>>(scores);
    // 5) attn[h] = P_h V_h             (tf32x3 NN, batched)
    gemm_t3(false, scores, TT, (long long)TT * TT, qkv + 2 * HH, 3 * HH, DHH, attn, HH, DHH,
            nullptr, 0, 0, TT, DHH, TT, 1.f, nullptr, NHH);
    // 6) x2 = x + attn @ w_o           (tf32x3 NN, fused residual)
    gemm_t3(false, attn, HH, 0, w_o, HH, 0, x2, HH, 0, x, HH, 0,
            TT, HH, HH, 1.f, nullptr, 1);
    // 7) post-LN -> fp32 (gate GEMM) + packed (MoE/shared path)
    rmsnorm_kernel<<<TT, 256>>>(x2, post_g, hn2, phn2);
    // 8) gate logits = hn2 @ w_gate^T  (tf32x3 NT — near-fp32, protects top-k)
    gemm_t3(true, hn2, HH, 0, w_gate, HH, 0, logits, EE, 0, nullptr, 0, 0,
            TT, EE, HH, 1.f, nullptr, 1);
    // 9) top-8 + weights
    gate_topk_kernel<<<TT, 32>>>(logits, ids, wts);
    // 10) capacity dispatch
    dispatch_kernel<<<EE, 256>>>(ids, pos, cnt);
    // 11) zero + gather packed rows
    zero_kernel<<<4096, 256>>>((uint4*)pbuf, (long long)EE * CAPP * HH / 4);
    gather_kernel<<<TT * KTOP, 256>>>(phn2, ids, pos, pbuf);
    // 12) expert GEMM1: gu[e] = buf[e] @ w1[e]^T   (bf16x3, count-guarded)
    gemm_b3(pbuf, HH, (long long)CAPP * HH, pw1, HH, (long long)2 * II * HH,
            gu, 2 * II, (long long)CAPP * 2 * II, nullptr, 0, 0,
            CAPP, 2 * II, HH, cnt, EE);
    // 13) silu(g)*u -> packed
    expert_act_kernel<<<EE * CAPP, 256>>>(gu, peact, cnt);
    // 14) expert GEMM2: y[e] = eact[e] @ w2[e]^T   (bf16x3, count-guarded)
    gemm_b3(peact, II, (long long)CAPP * II, pw2, II, (long long)HH * II,
            y, HH, (long long)CAPP * HH, nullptr, 0, 0,
            CAPP, HH, II, cnt, EE);
    // 15) shared MLP: sgu = hn2 @ w13^T            (bf16x3)
    gemm_b3(phn2, HH, 0, psw13, HH, 0, sgu, 2 * SII, 0, nullptr, 0, 0,
            TT, 2 * SII, HH, nullptr, 1);
    shared_act_kernel<<<TT, 256>>>(sgu, psact);
    // 16) sres = x2 + sact @ sw2^T                 (bf16x3, fused residual)
    gemm_b3(psact, SII, 0, psw2, SII, 0, sres, HH, 0, x2, HH, 0,
            TT, HH, SII, nullptr, 1);
    // 17) final combine
    combine_kernel<<<TT, 256>>>(sres, y, ids, wts, pos, out);
}

// round 16
// speedup vs baseline: 1.0019x; 1.0019x over previous
#include <cuda_runtime.h>
#include <cuda_bf16.h>
#include <cstdint>
#include <cstddef>

// ---------------- problem constants ----------------
constexpr int TT   = 2048;
constexpr int HH   = 2048;
constexpr int EE   = 64;
constexpr int KTOP = 8;
constexpr int II   = 768;
constexpr int NHH  = 16;
constexpr int DHH  = 128;
constexpr int SII  = 4096;
constexpr int CAPP = 512;

// ---------------- scratch (device globals: allocation-free) ----------------
// fp32
__device__ float g_hn1   [(size_t)TT*HH];
__device__ float g_qkv   [(size_t)TT*3*HH];
__device__ float g_scores[(size_t)NHH*TT*TT];
__device__ float g_attn  [(size_t)TT*HH];
__device__ float g_x2    [(size_t)TT*HH];
__device__ float g_hn2   [(size_t)TT*HH];
__device__ float g_logits[(size_t)TT*EE];
__device__ int   g_ids   [TT*KTOP];
__device__ float g_wts   [TT*KTOP];
__device__ int   g_pos   [TT*KTOP];
__device__ int   g_cnt   [EE];
__device__ float g_gu    [(size_t)EE*CAPP*2*II];
__device__ float g_y     [(size_t)EE*CAPP*HH];
__device__ float g_sgu   [(size_t)TT*2*SII];
__device__ float g_sres  [(size_t)TT*HH];
// packed bf16 hi/lo (hi in low 16 bits, lo in high 16 bits)
__device__ uint32_t p_hn2 [(size_t)TT*HH];
__device__ uint32_t p_buf [(size_t)EE*CAPP*HH];
__device__ uint32_t p_eact[(size_t)EE*CAPP*II];
__device__ uint32_t p_sact[(size_t)TT*SII];
__device__ uint32_t p_w1  [(size_t)EE*2*II*HH];
__device__ uint32_t p_w2  [(size_t)EE*HH*II];
__device__ uint32_t p_sw13[(size_t)2*SII*HH];
__device__ uint32_t p_sw2 [(size_t)HH*SII];

// ---------------- shared GEMM tiling ----------------
constexpr int BM  = 128, BN = 128, BKT = 16;
constexpr int ASTR   = BKT + 4;   // [row][k] tiles, stride 20 words
constexpr int BSTR_N = BN  + 8;   // tf32 NN B tile [k][n], stride 136

__device__ __forceinline__ uint32_t smaddr(const void* p) {
    return (uint32_t)__cvta_generic_to_shared(p);
}
__device__ __forceinline__ void cp16(uint32_t dst, const void* src, bool pred) {
    int sz = pred ? 16 : 0;
    asm volatile("cp.async.cg.shared.global [%0], [%1], 16, %2;\n"
                 :: "r"(dst), "l"(src), "r"(sz));
}
// split fp32 -> tf32 hi + tf32 lo (near-fp32 when recombined via 3 MMAs)
__device__ __forceinline__ void tf32split(float x, uint32_t& h, uint32_t& l) {
    asm("cvt.rna.tf32.f32 %0, %1;" : "=r"(h) : "f"(x));
    float r = x - __uint_as_float(h);
    asm("cvt.rna.tf32.f32 %0, %1;" : "=r"(l) : "f"(r));
}
// pack fp32 -> (bf16 hi | bf16 lo << 16)
__device__ __forceinline__ uint32_t packhl(float x) {
    __nv_bfloat16 hb = __float2bfloat16(x);
    unsigned hu = (unsigned)__bfloat16_as_ushort(hb);
    float hf = __uint_as_float(hu << 16);
    __nv_bfloat16 lb = __float2bfloat16(x - hf);
    unsigned lu = (unsigned)__bfloat16_as_ushort(lb);
    return hu | (lu << 16);
}
__device__ __forceinline__ void mma8_tf32(float c[4], const uint32_t a[4], const uint32_t b[2]) {
    asm volatile("mma.sync.aligned.m16n8k8.row.col.f32.tf32.tf32.f32 "
                 "{%0,%1,%2,%3}, {%4,%5,%6,%7}, {%8,%9}, {%0,%1,%2,%3};\n"
                 : "+f"(c[0]), "+f"(c[1]), "+f"(c[2]), "+f"(c[3])
                 : "r"(a[0]), "r"(a[1]), "r"(a[2]), "r"(a[3]),
                   "r"(b[0]), "r"(b[1]));
}
__device__ __forceinline__ void mma16_bf16(float c[4], const uint32_t a[4], const uint32_t b[2]) {
    asm volatile("mma.sync.aligned.m16n8k16.row.col.f32.bf16.bf16.f32 "
                 "{%0,%1,%2,%3}, {%4,%5,%6,%7}, {%8,%9}, {%0,%1,%2,%3};\n"
                 : "+f"(c[0]), "+f"(c[1]), "+f"(c[2]), "+f"(c[3])
                 : "r"(a[0]), "r"(a[1]), "r"(a[2]), "r"(a[3]),
                   "r"(b[0]), "r"(b[1]));
}

// ================= tf32x3 GEMM (fp32 in/out, near-fp32 accuracy) =================
// C[b] = alpha * A[b] * op(B[b]) (+ R[b]); op = B (KxN, !TB) or B^T (NxK rows, TB)
template <bool TB>
__global__ __launch_bounds__(256, 1)
void tgemm_tf32x3(const float* __restrict__ A, int lda, long long sA,
                  const float* __restrict__ B, int ldb, long long sB,
                  float*       __restrict__ C, int ldc, long long sC,
                  const float* __restrict__ R, int ldr, long long sR,
                  int M, int N, int Kd, float alpha,
                  const int* __restrict__ rowLimit)
{
    const int bz = blockIdx.z;
    if (rowLimit != nullptr && (int)(blockIdx.y * BM) >= rowLimit[bz]) return;
    A += (long long)bz * sA;
    B += (long long)bz * sB;
    C += (long long)bz * sC;
    if (R) R += (long long)bz * sR;

    constexpr int BS_ELEMS = TB ? BN * ASTR : BKT * BSTR_N;
    __shared__ float As[2][BM * ASTR];
    __shared__ float Bs[2][BS_ELEMS];

    const int tid  = threadIdx.x;
    const int lane = tid & 31;
    const int warp = tid >> 5;
    const int g    = lane >> 2;
    const int tg   = lane & 3;
    const int wm   = (warp & 3) * 32;
    const int wn   = (warp >> 2) * 64;
    const int row0 = blockIdx.y * BM;
    const int col0 = blockIdx.x * BN;

    float acc[2][8][4];
#pragma unroll
    for (int i = 0; i < 2; i++)
#pragma unroll
        for (int j = 0; j < 8; j++)
#pragma unroll
            for (int v = 0; v < 4; v++) acc[i][j][v] = 0.f;

    auto load_stage = [&](int k0, int bufi) {
        const int mr = tid >> 2;
        const int k4 = (tid & 3) * 4;
        {
            bool p0 = (row0 + mr) < M;
            cp16(smaddr(&As[bufi][mr * ASTR + k4]),
                 p0 ? A + (long long)(row0 + mr) * lda + k0 + k4 : A, p0);
            bool p1 = (row0 + mr + 64) < M;
            cp16(smaddr(&As[bufi][(mr + 64) * ASTR + k4]),
                 p1 ? A + (long long)(row0 + mr + 64) * lda + k0 + k4 : A, p1);
        }
        if (TB) {
            bool p0 = (col0 + mr) < N;
            cp16(smaddr(&Bs[bufi][mr * ASTR + k4]),
                 p0 ? B + (long long)(col0 + mr) * ldb + k0 + k4 : B, p0);
            bool p1 = (col0 + mr + 64) < N;
            cp16(smaddr(&Bs[bufi][(mr + 64) * ASTR + k4]),
                 p1 ? B + (long long)(col0 + mr + 64) * ldb + k0 + k4 : B, p1);
        } else {
            const int kr = tid >> 5;
            const int n4 = lane * 4;
            bool p = (col0 + n4) < N;
            cp16(smaddr(&Bs[bufi][kr * BSTR_N + n4]),
                 p ? B + (long long)(k0 + kr) * ldb + col0 + n4 : B, p);
            cp16(smaddr(&Bs[bufi][(kr + 8) * BSTR_N + n4]),
                 p ? B + (long long)(k0 + kr + 8) * ldb + col0 + n4 : B, p);
        }
    };

    load_stage(0, 0);
    asm volatile("cp.async.commit_group;\n");

    const int S = Kd >> 4;
    int buf = 0;
    for (int s = 0; s < S; s++) {
        asm volatile("cp.async.wait_group 0;\n");
        __syncthreads();
        if (s + 1 < S) {
            load_stage((s + 1) * BKT, buf ^ 1);
            asm volatile("cp.async.commit_group;\n");
        }
        const float* as = As[buf];
        const float* bs = Bs[buf];
#pragma unroll
        for (int ks = 0; ks < 2; ks++) {
            const int kb = ks * 8;
            uint32_t ah[2][4], al[2][4];
#pragma unroll
            for (int i = 0; i < 2; i++) {
                const int m = wm + i * 16 + g;
                tf32split(as[m       * ASTR + kb + tg],     ah[i][0], al[i][0]);
                tf32split(as[(m + 8) * ASTR + kb + tg],     ah[i][1], al[i][1]);
                tf32split(as[m       * ASTR + kb + tg + 4], ah[i][2], al[i][2]);
                tf32split(as[(m + 8) * ASTR + kb + tg + 4], ah[i][3], al[i][3]);
            }
#pragma unroll
            for (int j = 0; j < 8; j++) {
                const int n = wn + j * 8 + g;
                uint32_t bh[2], bl[2];
                if (TB) {
                    tf32split(bs[n * ASTR + kb + tg],     bh[0], bl[0]);
                    tf32split(bs[n * ASTR + kb + tg + 4], bh[1], bl[1]);
                } else {
                    tf32split(bs[(kb + tg)     * BSTR_N + n], bh[0], bl[0]);
                    tf32split(bs[(kb + tg + 4) * BSTR_N + n], bh[1], bl[1]);
                }
#pragma unroll
                for (int i = 0; i < 2; i++) {
                    mma8_tf32(acc[i][j], ah[i], bh);
                    mma8_tf32(acc[i][j], ah[i], bl);
                    mma8_tf32(acc[i][j], al[i], bh);
                }
            }
        }
        __syncthreads();
        buf ^= 1;
    }

#pragma unroll
    for (int i = 0; i < 2; i++) {
#pragma unroll
        for (int j = 0; j < 8; j++) {
            const int r = row0 + wm + i * 16 + g;
            const int c = col0 + wn + j * 8 + tg * 2;
            if (c < N) {
                if (r < M) {
                    float2 v = make_float2(alpha * acc[i][j][0], alpha * acc[i][j][1]);
                    if (R) {
                        const float2 rr = *reinterpret_cast<const float2*>(&R[(long long)r * ldr + c]);
                        v.x += rr.x; v.y += rr.y;
                    }
                    *reinterpret_cast<float2*>(&C[(long long)r * ldc + c]) = v;
                }
                if (r + 8 < M) {
                    float2 v = make_float2(alpha * acc[i][j][2], alpha * acc[i][j][3]);
                    if (R) {
                        const float2 rr = *reinterpret_cast<const float2*>(&R[(long long)(r + 8) * ldr + c]);
                        v.x += rr.x; v.y += rr.y;
                    }
                    *reinterpret_cast<float2*>(&C[(long long)(r + 8) * ldc + c]) = v;
                }
            }
        }
    }
}

// ================= bf16x3 GEMM (packed hi/lo in, fp32 out; TB only) =================
// C[b] = A[b] * B[b]^T (+ R[b]); A,B are packed uint32 (bf16 hi | bf16 lo<<16)
__global__ __launch_bounds__(256, 1)
void tgemm_bf16x3(const uint32_t* __restrict__ A, int lda, long long sA,
                  const uint32_t* __restrict__ B, int ldb, long long sB,
                  float*          __restrict__ C, int ldc, long long sC,
                  const float*    __restrict__ R, int ldr, long long sR,
                  int M, int N, int Kd,
                  const int* __restrict__ rowLimit)
{
    const int bz = blockIdx.z;
    if (rowLimit != nullptr && (int)(blockIdx.y * BM) >= rowLimit[bz]) return;
    A += (long long)bz * sA;
    B += (long long)bz * sB;
    C += (long long)bz * sC;
    if (R) R += (long long)bz * sR;

    __shared__ uint32_t As[2][BM * ASTR];
    __shared__ uint32_t Bs[2][BN * ASTR];

    const int tid  = threadIdx.x;
    const int lane = tid & 31;
    const int warp = tid >> 5;
    const int g    = lane >> 2;
    const int tg   = lane & 3;
    const int wm   = (warp & 3) * 32;
    const int wn   = (warp >> 2) * 64;
    const int row0 = blockIdx.y * BM;
    const int col0 = blockIdx.x * BN;

    float acc[2][8][4];
#pragma unroll
    for (int i = 0; i < 2; i++)
#pragma unroll
        for (int j = 0; j < 8; j++)
#pragma unroll
            for (int v = 0; v < 4; v++) acc[i][j][v] = 0.f;

    auto load_stage = [&](int k0, int bufi) {
        const int mr = tid >> 2;
        const int k4 = (tid & 3) * 4;
        bool p0 = (row0 + mr) < M;
        cp16(smaddr(&As[bufi][mr * ASTR + k4]),
             p0 ? A + (long long)(row0 + mr) * lda + k0 + k4 : A, p0);
        bool p1 = (row0 + mr + 64) < M;
        cp16(smaddr(&As[bufi][(mr + 64) * ASTR + k4]),
             p1 ? A + (long long)(row0 + mr + 64) * lda + k0 + k4 : A, p1);
        bool q0 = (col0 + mr) < N;
        cp16(smaddr(&Bs[bufi][mr * ASTR + k4]),
             q0 ? B + (long long)(col0 + mr) * ldb + k0 + k4 : B, q0);
        bool q1 = (col0 + mr + 64) < N;
        cp16(smaddr(&Bs[bufi][(mr + 64) * ASTR + k4]),
             q1 ? B + (long long)(col0 + mr + 64) * ldb + k0 + k4 : B, q1);
    };

    load_stage(0, 0);
    asm volatile("cp.async.commit_group;\n");

    const int S = Kd >> 4;
    int buf = 0;
    for (int s = 0; s < S; s++) {
        asm volatile("cp.async.wait_group 0;\n");
        __syncthreads();
        if (s + 1 < S) {
            load_stage((s + 1) * BKT, buf ^ 1);
            asm volatile("cp.async.commit_group;\n");
        }
        const uint32_t* as = As[buf];
        const uint32_t* bs = Bs[buf];

        uint32_t ah[2][4], al[2][4];
#pragma unroll
        for (int i = 0; i < 2; i++) {
            const int m = wm + i * 16 + g;
            uint2 w0 = *reinterpret_cast<const uint2*>(&as[m       * ASTR + 2 * tg]);
            uint2 w1 = *reinterpret_cast<const uint2*>(&as[(m + 8) * ASTR + 2 * tg]);
            uint2 w2 = *reinterpret_cast<const uint2*>(&as[m       * ASTR + 2 * tg + 8]);
            uint2 w3 = *reinterpret_cast<const uint2*>(&as[(m + 8) * ASTR + 2 * tg + 8]);
            ah[i][0] = __byte_perm(w0.x, w0.y, 0x5410); al[i][0] = __byte_perm(w0.x, w0.y, 0x7632);
            ah[i][1] = __byte_perm(w1.x, w1.y, 0x5410); al[i][1] = __byte_perm(w1.x, w1.y, 0x7632);
            ah[i][2] = __byte_perm(w2.x, w2.y, 0x5410); al[i][2] = __byte_perm(w2.x, w2.y, 0x7632);
            ah[i][3] = __byte_perm(w3.x, w3.y, 0x5410); al[i][3] = __byte_perm(w3.x, w3.y, 0x7632);
        }
#pragma unroll
        for (int j = 0; j < 8; j++) {
            const int n = wn + j * 8 + g;
            uint2 q0 = *reinterpret_cast<const uint2*>(&bs[n * ASTR + 2 * tg]);
            uint2 q1 = *reinterpret_cast<const uint2*>(&bs[n * ASTR + 2 * tg + 8]);
            uint32_t bh[2], bl[2];
            bh[0] = __byte_perm(q0.x, q0.y, 0x5410); bl[0] = __byte_perm(q0.x, q0.y, 0x7632);
            bh[1] = __byte_perm(q1.x, q1.y, 0x5410); bl[1] = __byte_perm(q1.x, q1.y, 0x7632);
#pragma unroll
            for (int i = 0; i < 2; i++) {
                mma16_bf16(acc[i][j], ah[i], bh);
                mma16_bf16(acc[i][j], ah[i], bl);
                mma16_bf16(acc[i][j], al[i], bh);
            }
        }
        __syncthreads();
        buf ^= 1;
    }

#pragma unroll
    for (int i = 0; i < 2; i++) {
#pragma unroll
        for (int j = 0; j < 8; j++) {
            const int r = row0 + wm + i * 16 + g;
            const int c = col0 + wn + j * 8 + tg * 2;
            if (c < N) {
                if (r < M) {
                    float2 v = make_float2(acc[i][j][0], acc[i][j][1]);
                    if (R) {
                        const float2 rr = *reinterpret_cast<const float2*>(&R[(long long)r * ldr + c]);
                        v.x += rr.x; v.y += rr.y;
                    }
                    *reinterpret_cast<float2*>(&C[(long long)r * ldc + c]) = v;
                }
                if (r + 8 < M) {
                    float2 v = make_float2(acc[i][j][2], acc[i][j][3]);
                    if (R) {
                        const float2 rr = *reinterpret_cast<const float2*>(&R[(long long)(r + 8) * ldr + c]);
                        v.x += rr.x; v.y += rr.y;
                    }
                    *reinterpret_cast<float2*>(&C[(long long)(r + 8) * ldc + c]) = v;
                }
            }
        }
    }
}

// ---------------- pack fp32 -> bf16 hi/lo uint32 ----------------
__global__ void pack_kernel(const float4* __restrict__ src, uint4* __restrict__ dst, long long n4)
{
    long long i = (long long)blockIdx.x * blockDim.x + threadIdx.x;
    long long stride = (long long)gridDim.x * blockDim.x;
    for (; i < n4; i += stride) {
        float4 v = src[i];
        uint4 o;
        o.x = packhl(v.x); o.y = packhl(v.y); o.z = packhl(v.z); o.w = packhl(v.w);
        dst[i] = o;
    }
}

// ---------------- RMSNorm (optional fp32 and packed outputs) ----------------
__global__ void rmsnorm_kernel(const float* __restrict__ x, const float* __restrict__ g,
                               float* __restrict__ outf, uint32_t* __restrict__ outp)
{
    int t = blockIdx.x, tid = threadIdx.x;
    const float* xr = x + (size_t)t * HH;
    __shared__ float red[256];
    float s = 0.f;
    for (int i = tid; i < HH; i += 256) { float v = xr[i]; s += v * v; }
    red[tid] = s; __syncthreads();
    for (int st = 128; st > 0; st >>= 1) { if (tid < st) red[tid] += red[tid + st]; __syncthreads(); }
    float inv = rsqrtf(red[0] / (float)HH + 1e-6f);
    for (int i = tid; i < HH; i += 256) {
        float v = xr[i] * inv * g[i];
        if (outf) outf[(size_t)t * HH + i] = v;
        if (outp) outp[(size_t)t * HH + i] = packhl(v);
    }
}

// ---------------- causal softmax (in-place on one hq row) ----------------
__global__ void softmax_causal_kernel(float* __restrict__ scores)
{
    size_t rowid = blockIdx.x;
    int q = (int)(rowid % TT);
    float* row = scores + rowid * (size_t)TT;
    int len = q + 1;
    int tid = threadIdx.x;
    __shared__ float red[256];

    float m = -3.4e38f;
    for (int i = tid; i < len; i += 256) m = fmaxf(m, row[i]);
    red[tid] = m; __syncthreads();
    for (int st = 128; st > 0; st >>= 1) { if (tid < st) red[tid] = fmaxf(red[tid], red[tid + st]); __syncthreads(); }
    m = red[0]; __syncthreads();

    float s = 0.f;
    for (int i = tid; i < len; i += 256) { float e = __expf(row[i] - m); row[i] = e; s += e; }
    red[tid] = s; __syncthreads();
    for (int st = 128; st > 0; st >>= 1) { if (tid < st) red[tid] += red[tid + st]; __syncthreads(); }
    float inv = 1.0f / red[0];

    for (int i = tid; i < len; i += 256) row[i] *= inv;
    for (int i = len + tid; i < TT; i += 256) row[i] = 0.f;
}

// ---------------- gating: top-8 on logits, softmax weights over selected ----------------
__global__ void gate_topk_kernel(const float* __restrict__ logits,
                                 int* __restrict__ ids, float* __restrict__ wts)
{
    int t = blockIdx.x, lane = threadIdx.x;
    float v0 = logits[(size_t)t * EE + lane];
    float v1 = logits[(size_t)t * EE + 32 + lane];
    float selv[KTOP]; int seli[KTOP];
    for (int r = 0; r < KTOP; r++) {
        float bv; int bi;
        if (v0 >= v1) { bv = v0; bi = lane; } else { bv = v1; bi = lane + 32; }
        for (int o = 16; o > 0; o >>= 1) {
            float ov = __shfl_xor_sync(0xffffffffu, bv, o);
            int   oi = __shfl_xor_sync(0xffffffffu, bi, o);
            if (ov > bv || (ov == bv && oi < bi)) { bv = ov; bi = oi; }
        }
        selv[r] = bv; seli[r] = bi;
        if (bi == lane)      v0 = -3.4e38f;
        if (bi == lane + 32) v1 = -3.4e38f;
    }
    if (lane == 0) {
        float m = selv[0], s = 0.f, w[KTOP];
        for (int r = 0; r < KTOP; r++) { w[r] = __expf(selv[r] - m); s += w[r]; }
        float inv = 1.f / s;
        for (int r = 0; r < KTOP; r++) { ids[t * KTOP + r] = seli[r]; wts[t * KTOP + r] = w[r] * inv; }
    }
}

// ---------------- per-expert capacity scan over flattened (t,k) order ----------------
__global__ void dispatch_kernel(const int* __restrict__ ids, int* __restrict__ pos,
                                int* __restrict__ cnt)
{
    int e = blockIdx.x;
    int tid = threadIdx.x, lane = tid & 31, w = tid >> 5;
    __shared__ int wt[8];
    __shared__ int base;
    if (tid == 0) base = 0;
    __syncthreads();
    for (int f0 = 0; f0 < TT * KTOP; f0 += 256) {
        int f = f0 + tid;
        int match = (ids[f] == e) ? 1 : 0;
        unsigned m = __ballot_sync(0xffffffffu, match);
        if (lane == 0) wt[w] = __popc(m);
        int wexcl = __popc(m & ((1u << lane) - 1u));
        __syncthreads();
        int off = 0; for (int i = 0; i < w; i++) off += wt[i];
        int tot = 0; for (int i = 0; i < 8; i++) tot += wt[i];
        if (match) {
            int p = base + off + wexcl;
            pos[f] = (p < CAPP) ? p : -1;
        }
        __syncthreads();
        if (tid == 0) base += tot;
        __syncthreads();
    }
    if (tid == 0) cnt[e] = (base < CAPP) ? base : CAPP;
}

// ---------------- zero / gather / activations / combine ----------------
__global__ void zero_kernel(uint4* __restrict__ p, long long n4)
{
    long long i = (long long)blockIdx.x * blockDim.x + threadIdx.x;
    long long stride = (long long)gridDim.x * blockDim.x;
    for (; i < n4; i += stride) p[i] = make_uint4(0u, 0u, 0u, 0u);
}

__global__ void gather_kernel(const uint32_t* __restrict__ hn2p, const int* __restrict__ ids,
                              const int* __restrict__ pos, uint32_t* __restrict__ buf)
{
    int f = blockIdx.x;
    int p = pos[f];
    if (p < 0) return;
    int e = ids[f], t = f / KTOP;
    const uint4* src = reinterpret_cast<const uint4*>(hn2p + (size_t)t * HH);
    uint4* dst = reinterpret_cast<uint4*>(buf + ((size_t)e * CAPP + p) * HH);
    for (int i = threadIdx.x; i < HH / 4; i += 256) dst[i] = src[i];
}

__global__ void expert_act_kernel(const float* __restrict__ gu, uint32_t* __restrict__ act,
                                  const int* __restrict__ cnt)
{
    int ec = blockIdx.x;
    int c = ec & (CAPP - 1);
    int e = ec >> 9;
    if (c >= cnt[e]) return;
    const float* gr = gu + (size_t)ec * (2 * II);
    uint32_t* ar = act + (size_t)ec * II;
    for (int i = threadIdx.x; i < II; i += 256) {
        float gv = gr[i], uv = gr[II + i];
        ar[i] = packhl(gv / (1.f + __expf(-gv)) * uv);
    }
}

__global__ void shared_act_kernel(const float* __restrict__ sgu, uint32_t* __restrict__ sact)
{
    int t = blockIdx.x;
    const float* gr = sgu + (size_t)t * (2 * SII);
    uint32_t* ar = sact + (size_t)t * SII;
    for (int i = threadIdx.x; i < SII; i += 256) {
        float gv = gr[i], uv = gr[SII + i];
        ar[i] = packhl(gv / (1.f + __expf(-gv)) * uv);
    }
}

__global__ void combine_kernel(const float* __restrict__ sres, const float* __restrict__ y,
                               const int* __restrict__ ids, const float* __restrict__ wts,
                               const int* __restrict__ pos, float* __restrict__ out)
{
    int t = blockIdx.x;
    __shared__ int se[KTOP], sp[KTOP];
    __shared__ float sw[KTOP];
    if (threadIdx.x < KTOP) {
        se[threadIdx.x] = ids[t * KTOP + threadIdx.x];
        sp[threadIdx.x] = pos[t * KTOP + threadIdx.x];
        sw[threadIdx.x] = wts[t * KTOP + threadIdx.x];
    }
    __syncthreads();
    for (int h = threadIdx.x; h < HH; h += 256) {
        float acc = sres[(size_t)t * HH + h];
#pragma unroll
        for (int k = 0; k < KTOP; k++)
            if (sp[k] >= 0)
                acc += y[((size_t)se[k] * CAPP + sp[k]) * HH + h] * sw[k];
        out[(size_t)t * HH + h] = acc;
    }
}

// ---------------- host-side launchers ----------------
static inline void gemm_t3(bool tb,
    const float* A, int lda, long long sA,
    const float* B, int ldb, long long sB,
    float*       C, int ldc, long long sC,
    const float* R, int ldr, long long sR,
    int M, int N, int Kd, float alpha, const int* rl, int batch)
{
    dim3 grid((N + BN - 1) / BN, (M + BM - 1) / BM, batch);
    if (tb) tgemm_tf32x3<true ><<<grid, 256>>>(A, lda, sA, B, ldb, sB, C, ldc, sC, R, ldr, sR, M, N, Kd, alpha, rl);
    else    tgemm_tf32x3<false><<<grid, 256>>>(A, lda, sA, B, ldb, sB, C, ldc, sC, R, ldr, sR, M, N, Kd, alpha, rl);
}
static inline void gemm_b3(
    const uint32_t* A, int lda, long long sA,
    const uint32_t* B, int ldb, long long sB,
    float*          C, int ldc, long long sC,
    const float*    R, int ldr, long long sR,
    int M, int N, int Kd, const int* rl, int batch)
{
    dim3 grid((N + BN - 1) / BN, (M + BM - 1) / BM, batch);
    tgemm_bf16x3<<<grid, 256>>>(A, lda, sA, B, ldb, sB, C, ldc, sC, R, ldr, sR, M, N, Kd, rl);
}

extern "C" void kernel_launch(void* const* d_in, const int* in_sizes, int n_in,
                              void* d_out, int out_size)
{
    const float* x      = (const float*)d_in[0];
    const float* w_qkv  = (const float*)d_in[1];
    const float* w_o    = (const float*)d_in[2];
    const float* pre_g  = (const float*)d_in[3];
    const float* post_g = (const float*)d_in[4];
    const float* w_gate = (const float*)d_in[5];
    const float* w1     = (const float*)d_in[6];
    const float* w2     = (const float*)d_in[7];
    const float* sw13   = (const float*)d_in[8];
    const float* sw2    = (const float*)d_in[9];
    float* out = (float*)d_out;

    float *hn1, *qkv, *scores, *attn, *x2, *hn2, *logits, *wts, *gu, *y, *sgu, *sres;
    int *ids, *pos, *cnt;
    uint32_t *phn2, *pbuf, *peact, *psact, *pw1, *pw2, *psw13, *psw2;
    cudaGetSymbolAddress((void**)&hn1,    g_hn1);
    cudaGetSymbolAddress((void**)&qkv,    g_qkv);
    cudaGetSymbolAddress((void**)&scores, g_scores);
    cudaGetSymbolAddress((void**)&attn,   g_attn);
    cudaGetSymbolAddress((void**)&x2,     g_x2);
    cudaGetSymbolAddress((void**)&hn2,    g_hn2);
    cudaGetSymbolAddress((void**)&logits, g_logits);
    cudaGetSymbolAddress((void**)&ids,    g_ids);
    cudaGetSymbolAddress((void**)&wts,    g_wts);
    cudaGetSymbolAddress((void**)&pos,    g_pos);
    cudaGetSymbolAddress((void**)&cnt,    g_cnt);
    cudaGetSymbolAddress((void**)&gu,     g_gu);
    cudaGetSymbolAddress((void**)&y,      g_y);
    cudaGetSymbolAddress((void**)&sgu,    g_sgu);
    cudaGetSymbolAddress((void**)&sres,   g_sres);
    cudaGetSymbolAddress((void**)&phn2,   p_hn2);
    cudaGetSymbolAddress((void**)&pbuf,   p_buf);
    cudaGetSymbolAddress((void**)&peact,  p_eact);
    cudaGetSymbolAddress((void**)&psact,  p_sact);
    cudaGetSymbolAddress((void**)&pw1,    p_w1);
    cudaGetSymbolAddress((void**)&pw2,    p_w2);
    cudaGetSymbolAddress((void**)&psw13,  p_sw13);
    cudaGetSymbolAddress((void**)&psw2,   p_sw2);

    const float sc = 0.08838834764831845f;   // DH^-0.5

    // 0) pack MoE/shared weights into bf16 hi/lo
    pack_kernel<<<4096, 256>>>((const float4*)w1,   (uint4*)pw1,   (long long)EE * 2 * II * HH / 4);
    pack_kernel<<<4096, 256>>>((const float4*)w2,   (uint4*)pw2,   (long long)EE * HH * II / 4);
    pack_kernel<<<2048, 256>>>((const float4*)sw13, (uint4*)psw13, (long long)2 * SII * HH / 4);
    pack_kernel<<<2048, 256>>>((const float4*)sw2,  (uint4*)psw2,  (long long)HH * SII / 4);

    // 1) pre-LN (fp32 only; consumed by tf32x3 qkv GEMM)
    rmsnorm_kernel<<<TT, 256>>>(x, pre_g, hn1, nullptr);
    // 2) qkv = hn1 @ w_qkv             (tf32x3 NN)
    gemm_t3(false, hn1, HH, 0, w_qkv, 3 * HH, 0, qkv, 3 * HH, 0, nullptr, 0, 0,
            TT, 3 * HH, HH, 1.f, nullptr, 1);
    // 3) scores[h] = Q_h K_h^T * sc    (tf32x3 NT, batched over heads)
    gemm_t3(true, qkv, 3 * HH, DHH, qkv + HH, 3 * HH, DHH, scores, TT, (long long)TT * TT,
            nullptr, 0, 0, TT, TT, DHH, sc, nullptr, NHH);
    // 4) causal softmax in-place
    softmax_causal_kernel<<<NHH * TT, 256>>>(scores);
    // 5) attn[h] = P_h V_h             (tf32x3 NN, batched)
    gemm_t3(false, scores, TT, (long long)TT * TT, qkv + 2 * HH, 3 * HH, DHH, attn, HH, DHH,
            nullptr, 0, 0, TT, DHH, TT, 1.f, nullptr, NHH);
    // 6) x2 = x + attn @ w_o           (tf32x3 NN, fused residual)
    gemm_t3(false, attn, HH, 0, w_o, HH, 0, x2, HH, 0, x, HH, 0,
            TT, HH, HH, 1.f, nullptr, 1);
    // 7) post-LN -> fp32 (gate GEMM) + packed (MoE/shared path)
    rmsnorm_kernel<<<TT, 256>>>(x2, post_g, hn2, phn2);
    // 8) gate logits = hn2 @ w_gate^T  (tf32x3 NT — near-fp32, protects top-k)
    gemm_t3(true, hn2, HH, 0, w_gate, HH, 0, logits, EE, 0, nullptr, 0, 0,
            TT, EE, HH, 1.f, nullptr, 1);
    // 9) top-8 + weights
    gate_topk_kernel<<<TT, 32>>>(logits, ids, wts);
    // 10) capacity dispatch
    dispatch_kernel<<<EE, 256>>>(ids, pos, cnt);
    // 11) zero + gather packed rows
    zero_kernel<<<4096, 256>>>((uint4*)pbuf, (long long)EE * CAPP * HH / 4);
    gather_kernel<<<TT * KTOP, 256>>>(phn2, ids, pos, pbuf);
    // 12) expert GEMM1: gu[e] = buf[e] @ w1[e]^T   (bf16x3, count-guarded)
    gemm_b3(pbuf, HH, (long long)CAPP * HH, pw1, HH, (long long)2 * II * HH,
            gu, 2 * II, (long long)CAPP * 2 * II, nullptr, 0, 0,
            CAPP, 2 * II, HH, cnt, EE);
    // 13) silu(g)*u -> packed
    expert_act_kernel<<<EE * CAPP, 256>>>(gu, peact, cnt);
    // 14) expert GEMM2: y[e] = eact[e] @ w2[e]^T   (bf16x3, count-guarded)
    gemm_b3(peact, II, (long long)CAPP * II, pw2, II, (long long)HH * II,
            y, HH, (long long)CAPP * HH, nullptr, 0, 0,
            CAPP, HH, II, cnt, EE);
    // 15) shared MLP: sgu = hn2 @ w13^T            (bf16x3)
    gemm_b3(phn2, HH, 0, psw13, HH, 0, sgu, 2 * SII, 0, nullptr, 0, 0,
            TT, 2 * SII, HH, nullptr, 1);
    shared_act_kernel<<<TT, 256>>>(sgu, psact);
    // 16) sres = x2 + sact @ sw2^T                 (bf16x3, fused residual)
    gemm_b3(psact, SII, 0, psw2, SII, 0, sres, HH, 0, x2, HH, 0,
            TT, HH, SII, nullptr, 1);
    // 17) final combine
    combine_kernel<<<TT, 256>>>(sres, y, ids, wts, pos, out);
}